// round 1
// baseline (speedup 1.0000x reference)
#include <cuda_runtime.h>
#include <math.h>

#define D_MODEL 768
#define D_INNER 1536
#define D_STATE 16
#define D_CONV  4
#define DT_RANK 48
#define BATCH   2
#define SEQ     2048
#define NTOK    (BATCH*SEQ)
#define XPROJ   80
#define CHUNK   64

// ---------------- scratch (static device globals; no allocs) ----------------
static __device__ float g_xz  [2][NTOK][2*D_INNER];  // in_proj output (x | z)
static __device__ float g_xc  [2][NTOK][D_INNER];    // conv+silu output
static __device__ float g_xdbl[2][NTOK][XPROJ];      // x_proj output (dt_r | B | C)
static __device__ float g_dt  [2][NTOK][D_INNER];    // softplus(dt)
static __device__ float g_y   [2][NTOK][D_INNER];    // scan output, gated

__device__ __forceinline__ float siluf(float v)     { return v / (1.f + __expf(-v)); }
__device__ __forceinline__ float softplusf(float v) { return fmaxf(v, 0.f) + log1pf(__expf(-fabsf(v))); }

// ---------------------------------------------------------------------------
// Generic GEMM:  C[M,N] = A[M,K](row-major, lda) * B[N,K](row-major, ldb)^T
// mode 0: store   mode 1: accumulate into C   mode 2: softplus(acc + bias[n])
// BM=BN=128, BK=8, 256 threads, 8x8 micro-tile.
// Requires: M % 128 == 0, K % 8 == 0, lda/ldb % 4 == 0. N arbitrary (guarded).
// ---------------------------------------------------------------------------
__global__ void __launch_bounds__(256, 2) gemm_nt(
    const float* __restrict__ A, int lda,
    const float* __restrict__ B, int ldb,
    float* __restrict__ C, int ldc,
    int M, int N, int K,
    const float* __restrict__ bias, int mode)
{
    const int BM = 128, BN = 128, BK = 8;
    __shared__ float As[BK][BM + 4];
    __shared__ float Bs[BK][BN + 4];

    int tid = threadIdx.x;
    int bm = blockIdx.y * BM;
    int bn = blockIdx.x * BN;
    int ty = tid >> 4;          // 0..15  (row group)
    int tx = tid & 15;          // 0..15  (col group)
    int lrow = tid >> 1;        // 0..127 row within tile for loads
    int lc4  = (tid & 1) * 4;   // 0 or 4 (float4 column offset)

    float acc[8][8];
#pragma unroll
    for (int i = 0; i < 8; i++)
#pragma unroll
        for (int j = 0; j < 8; j++) acc[i][j] = 0.f;

    for (int k0 = 0; k0 < K; k0 += BK) {
        float4 av = *(const float4*)(A + (size_t)(bm + lrow) * lda + k0 + lc4);
        float4 bv = make_float4(0.f, 0.f, 0.f, 0.f);
        int nb = bn + lrow;
        if (nb < N) bv = *(const float4*)(B + (size_t)nb * ldb + k0 + lc4);

        As[lc4 + 0][lrow] = av.x; As[lc4 + 1][lrow] = av.y;
        As[lc4 + 2][lrow] = av.z; As[lc4 + 3][lrow] = av.w;
        Bs[lc4 + 0][lrow] = bv.x; Bs[lc4 + 1][lrow] = bv.y;
        Bs[lc4 + 2][lrow] = bv.z; Bs[lc4 + 3][lrow] = bv.w;
        __syncthreads();

#pragma unroll
        for (int k = 0; k < BK; k++) {
            float a[8], b[8];
#pragma unroll
            for (int i = 0; i < 8; i++) a[i] = As[k][ty * 8 + i];
#pragma unroll
            for (int j = 0; j < 8; j++) b[j] = Bs[k][tx * 8 + j];
#pragma unroll
            for (int i = 0; i < 8; i++)
#pragma unroll
                for (int j = 0; j < 8; j++)
                    acc[i][j] = fmaf(a[i], b[j], acc[i][j]);
        }
        __syncthreads();
    }

#pragma unroll
    for (int i = 0; i < 8; i++) {
        int m = bm + ty * 8 + i;
#pragma unroll
        for (int j = 0; j < 8; j++) {
            int n = bn + tx * 8 + j;
            if (n < N) {
                size_t idx = (size_t)m * ldc + n;
                float v = acc[i][j];
                if (mode == 2)      v = softplusf(v + bias[n]);
                else if (mode == 1) v += C[idx];
                C[idx] = v;
            }
        }
    }
}

// ---------------------------------------------------------------------------
// Depthwise causal conv (D_CONV=4) + bias + SiLU, for both directions.
// dir 0 (forward): taps t-3+k ; dir 1 (reverse pipeline on unreversed data):
// taps t+3-k. Out-of-range taps are zero (padding).
// ---------------------------------------------------------------------------
__global__ void __launch_bounds__(256) conv_silu_kernel(
    const float* __restrict__ w_f, const float* __restrict__ b_f,
    const float* __restrict__ w_r, const float* __restrict__ b_r)
{
    int d = blockIdx.x * 256 + threadIdx.x;
    int t = blockIdx.y;
    int zb = blockIdx.z;
    int dir = zb >> 1, b = zb & 1;

    const float* w  = dir ? w_r : w_f;
    float acc = (dir ? b_r : b_f)[d];
#pragma unroll
    for (int k = 0; k < D_CONV; k++) {
        int tt = dir ? (t + (D_CONV - 1) - k) : (t - (D_CONV - 1) + k);
        if (tt >= 0 && tt < SEQ)
            acc = fmaf(w[d * D_CONV + k], g_xz[dir][b * SEQ + tt][d], acc);
    }
    g_xc[dir][b * SEQ + t][d] = siluf(acc);
}

// ---------------------------------------------------------------------------
// Selective scan. One thread per (dir, b, d) channel, sequential over SEQ.
// B_t / C_t (shared across d) are staged in SMEM per 64-step chunk.
// dir 1 iterates time descending (reversal of output cancels input reversal).
// ---------------------------------------------------------------------------
__global__ void __launch_bounds__(128) scan_kernel(
    const float* __restrict__ Alog_f, const float* __restrict__ D_f,
    const float* __restrict__ Alog_r, const float* __restrict__ D_r)
{
    int dir = blockIdx.z;
    int b   = blockIdx.y;
    int d   = blockIdx.x * 128 + threadIdx.x;

    const float* Alog = dir ? Alog_r : Alog_f;
    float Av[D_STATE];
#pragma unroll
    for (int n = 0; n < D_STATE; n++) Av[n] = -__expf(Alog[d * D_STATE + n]);
    float Dv = (dir ? D_r : D_f)[d];

    float h[D_STATE];
#pragma unroll
    for (int n = 0; n < D_STATE; n++) h[n] = 0.f;

    __shared__ float sB[CHUNK][D_STATE];
    __shared__ float sC[CHUNK][D_STATE];

    for (int c = 0; c < SEQ / CHUNK; c++) {
        // cooperative load of B/C for this chunk (32 floats per timestep)
        for (int j = threadIdx.x; j < CHUNK * 2 * D_STATE; j += 128) {
            int lt = j >> 5;
            int cc = j & 31;
            int t = dir ? (SEQ - 1 - (c * CHUNK + lt)) : (c * CHUNK + lt);
            float v = g_xdbl[dir][b * SEQ + t][DT_RANK + cc];
            if (cc < D_STATE) sB[lt][cc] = v;
            else              sC[lt][cc - D_STATE] = v;
        }
        __syncthreads();

        for (int lt = 0; lt < CHUNK; lt++) {
            int t   = dir ? (SEQ - 1 - (c * CHUNK + lt)) : (c * CHUNK + lt);
            int tok = b * SEQ + t;
            float dt  = g_dt[dir][tok][d];
            float x   = g_xc[dir][tok][d];
            float dtx = dt * x;
            float y = 0.f;
#pragma unroll
            for (int n = 0; n < D_STATE; n++) {
                float dA = __expf(dt * Av[n]);
                h[n] = fmaf(dA, h[n], dtx * sB[lt][n]);
                y    = fmaf(h[n], sC[lt][n], y);
            }
            float z = g_xz[dir][tok][D_INNER + d];
            g_y[dir][tok][d] = (y + x * Dv) * siluf(z);
        }
        __syncthreads();
    }
}

// ---------------------------------------------------------------------------
extern "C" void kernel_launch(void* const* d_in, const int* in_sizes, int n_in,
                              void* d_out, int out_size)
{
    (void)in_sizes; (void)n_in; (void)out_size;

    const float* hidden   = (const float*)d_in[0];
    const float* inW[2]   = {(const float*)d_in[1],  (const float*)d_in[10]};
    const float* convW[2] = {(const float*)d_in[2],  (const float*)d_in[11]};
    const float* convB[2] = {(const float*)d_in[3],  (const float*)d_in[12]};
    const float* xpW[2]   = {(const float*)d_in[4],  (const float*)d_in[13]};
    const float* dtW[2]   = {(const float*)d_in[5],  (const float*)d_in[14]};
    const float* dtB[2]   = {(const float*)d_in[6],  (const float*)d_in[15]};
    const float* Alog[2]  = {(const float*)d_in[7],  (const float*)d_in[16]};
    const float* Dp[2]    = {(const float*)d_in[8],  (const float*)d_in[17]};
    const float* outW[2]  = {(const float*)d_in[9],  (const float*)d_in[18]};
    float* out = (float*)d_out;

    float *xz, *xc, *xdbl, *dt, *y;
    cudaGetSymbolAddress((void**)&xz,   g_xz);
    cudaGetSymbolAddress((void**)&xc,   g_xc);
    cudaGetSymbolAddress((void**)&xdbl, g_xdbl);
    cudaGetSymbolAddress((void**)&dt,   g_dt);
    cudaGetSymbolAddress((void**)&y,    g_y);

    const size_t szXZ   = (size_t)NTOK * 2 * D_INNER;
    const size_t szXC   = (size_t)NTOK * D_INNER;
    const size_t szXDBL = (size_t)NTOK * XPROJ;

    // 1) in_proj: [4096,768] x [3072,768]^T -> [4096,3072]  (per dir)
    for (int dir = 0; dir < 2; dir++) {
        gemm_nt<<<dim3((2 * D_INNER) / 128, NTOK / 128), 256>>>(
            hidden, D_MODEL, inW[dir], D_MODEL,
            xz + dir * szXZ, 2 * D_INNER,
            NTOK, 2 * D_INNER, D_MODEL, nullptr, 0);
    }

    // 2) depthwise conv + silu (both dirs)
    conv_silu_kernel<<<dim3(D_INNER / 256, SEQ, 4), 256>>>(
        convW[0], convB[0], convW[1], convB[1]);

    // 3) x_proj: [4096,1536] x [80,1536]^T -> [4096,80]  (per dir)
    for (int dir = 0; dir < 2; dir++) {
        gemm_nt<<<dim3(1, NTOK / 128), 256>>>(
            xc + dir * szXC, D_INNER, xpW[dir], D_INNER,
            xdbl + dir * szXDBL, XPROJ,
            NTOK, XPROJ, D_INNER, nullptr, 0);
    }

    // 4) dt_proj + bias + softplus: [4096,48] x [1536,48]^T -> [4096,1536]
    for (int dir = 0; dir < 2; dir++) {
        gemm_nt<<<dim3(D_INNER / 128, NTOK / 128), 256>>>(
            xdbl + dir * szXDBL, XPROJ, dtW[dir], DT_RANK,
            dt + dir * szXC, D_INNER,
            NTOK, D_INNER, DT_RANK, dtB[dir], 2);
    }

    // 5) selective scan + skip + gate (both dirs)
    scan_kernel<<<dim3(D_INNER / 128, BATCH, 2), 128>>>(
        Alog[0], Dp[0], Alog[1], Dp[1]);

    // 6) out_proj: [4096,1536] x [768,1536]^T -> [4096,768]; dir0 store, dir1 add
    gemm_nt<<<dim3(D_MODEL / 128, NTOK / 128), 256>>>(
        y, D_INNER, outW[0], D_INNER, out, D_MODEL,
        NTOK, D_MODEL, D_INNER, nullptr, 0);
    gemm_nt<<<dim3(D_MODEL / 128, NTOK / 128), 256>>>(
        y + szXC, D_INNER, outW[1], D_INNER, out, D_MODEL,
        NTOK, D_MODEL, D_INNER, nullptr, 1);
}

// round 4
// speedup vs baseline: 1.6947x; 1.6947x over previous
#include <cuda_runtime.h>
#include <math.h>
#include <stdint.h>

#define D_MODEL 768
#define D_INNER 1536
#define D_STATE 16
#define D_CONV  4
#define DT_RANK 48
#define BATCH   2
#define SEQ     2048
#define NTOK    (BATCH*SEQ)
#define XPROJ   80
#define CHUNK   64

#define BK      16
#define ASTR    20   // padded smem row stride (floats): conflict-free quads

// ---------------- scratch (static device globals; no allocs) ----------------
static __device__ float g_xz  [2][NTOK][2*D_INNER];
static __device__ float g_xc  [2][NTOK][D_INNER];
static __device__ float g_xdbl[2][NTOK][XPROJ];
static __device__ float g_dt  [2][NTOK][D_INNER];
static __device__ float g_y   [2][NTOK][D_INNER];

__device__ __forceinline__ float siluf(float v)     { return v / (1.f + __expf(-v)); }
__device__ __forceinline__ float softplusf(float v) { return fmaxf(v, 0.f) + log1pf(__expf(-fabsf(v))); }
__device__ __forceinline__ uint32_t f2tf32(float f) {
    uint32_t r; asm("cvt.rna.tf32.f32 %0, %1;" : "=r"(r) : "f"(f)); return r;
}
__device__ __forceinline__ void mma8(float* d, const uint32_t* a, const uint32_t* b) {
    asm volatile(
        "mma.sync.aligned.m16n8k8.row.col.f32.tf32.tf32.f32 "
        "{%0,%1,%2,%3}, {%4,%5,%6,%7}, {%8,%9}, {%0,%1,%2,%3};"
        : "+f"(d[0]), "+f"(d[1]), "+f"(d[2]), "+f"(d[3])
        : "r"(a[0]), "r"(a[1]), "r"(a[2]), "r"(a[3]), "r"(b[0]), "r"(b[1]));
}

// ---------------------------------------------------------------------------
// Tensor-core GEMM:  C[M,Nfull] = A[M,K] * B[Nfull,K]^T  (tiles 128x128)
// A/B given as two K-segments (k<Ksplit -> seg0, else seg1), selected per
// dir = blockIdx.z. mode 0: store; mode 2: softplus(v + bias[n]).
// Requires: M%128==0, K%16==0, lda/ldb%4==0.
// ---------------------------------------------------------------------------
__global__ void __launch_bounds__(256) gemm_tc(
    const float* Aa0, const float* Aa1, const float* Ab0, const float* Ab1,
    int lda, int Ksplit,
    const float* Ba0, const float* Ba1, const float* Bb0, const float* Bb1,
    int ldb,
    float* C, long long cDirStride, int ldc,
    int Nfull, int Ktot,
    const float* bias0, const float* bias1, int mode)
{
    __shared__ float As[2][128][ASTR];
    __shared__ float Bs[2][128][ASTR];

    const int tid    = threadIdx.x;
    const int lane   = tid & 31;
    const int wid    = tid >> 5;
    const int warp_m = wid & 1;          // 0..1 -> 64 rows
    const int warp_n = wid >> 1;         // 0..3 -> 32 cols
    const int g      = lane >> 2;        // fragment row group 0..7
    const int t      = lane & 3;         // fragment col group 0..3
    const int dir    = blockIdx.z;
    const int bm     = blockIdx.y * 128;
    const int bn     = blockIdx.x * 128;

    const float* Aseg0 = dir ? Aa1 : Aa0;
    const float* Aseg1 = dir ? Ab1 : Ab0;
    const float* Bseg0 = dir ? Ba1 : Ba0;
    const float* Bseg1 = dir ? Bb1 : Bb0;
    const float* bias  = dir ? bias1 : bias0;
    float* Cd = C + (long long)dir * cDirStride;

    // per-thread staging coordinates: 2 float4 per tile (A and B)
    const int ar[2] = { (0 * 256 + tid) >> 2, (1 * 256 + tid) >> 2 };   // smem row
    const int ac    = (tid & 3) * 4;                                     // smem col

    float acc[4][4][4];
#pragma unroll
    for (int mi = 0; mi < 4; mi++)
#pragma unroll
        for (int ni = 0; ni < 4; ni++)
#pragma unroll
            for (int r = 0; r < 4; r++) acc[mi][ni][r] = 0.f;

    const int nch = Ktot / BK;
    float4 stA[2], stB[2];

    // ---- stage loader (global -> regs) ----
    auto stage = [&](int c) {
        const int k0 = c * BK + ac;
        const float* Asrc = Aseg0; int ka = k0;
        if (k0 >= Ksplit) { Asrc = Aseg1; ka = k0 - Ksplit; }
        const float* Bsrc = Bseg0; int kb = k0;
        if (k0 >= Ksplit) { Bsrc = Bseg1; kb = k0 - Ksplit; }
#pragma unroll
        for (int i = 0; i < 2; i++) {
            stA[i] = *(const float4*)(Asrc + (size_t)(bm + ar[i]) * lda + ka);
            int nb = bn + ar[i];
            stB[i] = (nb < Nfull)
                ? *(const float4*)(Bsrc + (size_t)nb * ldb + kb)
                : make_float4(0.f, 0.f, 0.f, 0.f);
        }
    };
    // ---- stage writer (regs -> smem, tf32-rounded) ----
    auto commit = [&](int nb) {
#pragma unroll
        for (int i = 0; i < 2; i++) {
            uint4 a = make_uint4(f2tf32(stA[i].x), f2tf32(stA[i].y),
                                 f2tf32(stA[i].z), f2tf32(stA[i].w));
            uint4 b = make_uint4(f2tf32(stB[i].x), f2tf32(stB[i].y),
                                 f2tf32(stB[i].z), f2tf32(stB[i].w));
            *(uint4*)&As[nb][ar[i]][ac] = a;
            *(uint4*)&Bs[nb][ar[i]][ac] = b;
        }
    };

    stage(0);
    commit(0);
    __syncthreads();

    for (int c = 0; c < nch; c++) {
        const int b = c & 1;
        if (c + 1 < nch) stage(c + 1);

        const float (*A_)[ASTR] = As[b];
        const float (*B_)[ASTR] = Bs[b];
#pragma unroll
        for (int ks = 0; ks < 2; ks++) {
            const int k8 = ks * 8;
            uint32_t af[4][4], bf[4][2];
#pragma unroll
            for (int mi = 0; mi < 4; mi++) {
                int r = warp_m * 64 + mi * 16 + g;
                af[mi][0] = __float_as_uint(A_[r    ][k8 + t    ]);
                af[mi][1] = __float_as_uint(A_[r + 8][k8 + t    ]);
                af[mi][2] = __float_as_uint(A_[r    ][k8 + t + 4]);
                af[mi][3] = __float_as_uint(A_[r + 8][k8 + t + 4]);
            }
#pragma unroll
            for (int ni = 0; ni < 4; ni++) {
                int r = warp_n * 32 + ni * 8 + g;
                bf[ni][0] = __float_as_uint(B_[r][k8 + t    ]);
                bf[ni][1] = __float_as_uint(B_[r][k8 + t + 4]);
            }
#pragma unroll
            for (int mi = 0; mi < 4; mi++)
#pragma unroll
                for (int ni = 0; ni < 4; ni++)
                    mma8(acc[mi][ni], af[mi], bf[ni]);
        }

        if (c + 1 < nch) commit(b ^ 1);
        __syncthreads();
    }

    // ---- epilogue: registers -> gmem (float2 per row-half) ----
#pragma unroll
    for (int mi = 0; mi < 4; mi++) {
        int row = bm + warp_m * 64 + mi * 16 + g;
#pragma unroll
        for (int ni = 0; ni < 4; ni++) {
            int col = bn + warp_n * 32 + ni * 8 + t * 2;
            if (col < Nfull) {
                float2 v0 = make_float2(acc[mi][ni][0], acc[mi][ni][1]);
                float2 v1 = make_float2(acc[mi][ni][2], acc[mi][ni][3]);
                if (mode == 2) {
                    float b0 = bias[col], b1 = bias[col + 1];
                    v0.x = softplusf(v0.x + b0); v0.y = softplusf(v0.y + b1);
                    v1.x = softplusf(v1.x + b0); v1.y = softplusf(v1.y + b1);
                }
                *(float2*)(Cd + (size_t)row * ldc + col)        = v0;
                *(float2*)(Cd + (size_t)(row + 8) * ldc + col)  = v1;
            }
        }
    }
}

// ---------------------------------------------------------------------------
// Depthwise causal conv (D_CONV=4) + bias + SiLU, both directions.
// ---------------------------------------------------------------------------
__global__ void __launch_bounds__(256) conv_silu_kernel(
    const float* __restrict__ w_f, const float* __restrict__ b_f,
    const float* __restrict__ w_r, const float* __restrict__ b_r)
{
    int d = blockIdx.x * 256 + threadIdx.x;
    int t = blockIdx.y;
    int zb = blockIdx.z;
    int dir = zb >> 1, b = zb & 1;

    const float* w  = dir ? w_r : w_f;
    float acc = (dir ? b_r : b_f)[d];
#pragma unroll
    for (int k = 0; k < D_CONV; k++) {
        int tt = dir ? (t + (D_CONV - 1) - k) : (t - (D_CONV - 1) + k);
        if (tt >= 0 && tt < SEQ)
            acc = fmaf(w[d * D_CONV + k], g_xz[dir][b * SEQ + tt][d], acc);
    }
    g_xc[dir][b * SEQ + t][d] = siluf(acc);
}

// ---------------------------------------------------------------------------
// Selective scan. One thread per (dir, b, d) channel, sequential over SEQ.
// ---------------------------------------------------------------------------
__global__ void __launch_bounds__(128) scan_kernel(
    const float* __restrict__ Alog_f, const float* __restrict__ D_f,
    const float* __restrict__ Alog_r, const float* __restrict__ D_r)
{
    int dir = blockIdx.z;
    int b   = blockIdx.y;
    int d   = blockIdx.x * 128 + threadIdx.x;

    const float* Alog = dir ? Alog_r : Alog_f;
    float Av[D_STATE];
#pragma unroll
    for (int n = 0; n < D_STATE; n++) Av[n] = -__expf(Alog[d * D_STATE + n]);
    float Dv = (dir ? D_r : D_f)[d];

    float h[D_STATE];
#pragma unroll
    for (int n = 0; n < D_STATE; n++) h[n] = 0.f;

    __shared__ float sB[CHUNK][D_STATE];
    __shared__ float sC[CHUNK][D_STATE];

    for (int c = 0; c < SEQ / CHUNK; c++) {
        for (int j = threadIdx.x; j < CHUNK * 2 * D_STATE; j += 128) {
            int lt = j >> 5;
            int cc = j & 31;
            int t = dir ? (SEQ - 1 - (c * CHUNK + lt)) : (c * CHUNK + lt);
            float v = g_xdbl[dir][b * SEQ + t][DT_RANK + cc];
            if (cc < D_STATE) sB[lt][cc] = v;
            else              sC[lt][cc - D_STATE] = v;
        }
        __syncthreads();

        for (int lt = 0; lt < CHUNK; lt++) {
            int tt  = dir ? (SEQ - 1 - (c * CHUNK + lt)) : (c * CHUNK + lt);
            int tok = b * SEQ + tt;
            float dt  = g_dt[dir][tok][d];
            float x   = g_xc[dir][tok][d];
            float dtx = dt * x;
            float y = 0.f;
#pragma unroll
            for (int n = 0; n < D_STATE; n++) {
                float dA = __expf(dt * Av[n]);
                h[n] = fmaf(dA, h[n], dtx * sB[lt][n]);
                y    = fmaf(h[n], sC[lt][n], y);
            }
            float z = g_xz[dir][tok][D_INNER + d];
            g_y[dir][tok][d] = (y + x * Dv) * siluf(z);
        }
        __syncthreads();
    }
}

// ---------------------------------------------------------------------------
extern "C" void kernel_launch(void* const* d_in, const int* in_sizes, int n_in,
                              void* d_out, int out_size)
{
    (void)in_sizes; (void)n_in; (void)out_size;

    const float* hidden   = (const float*)d_in[0];
    const float* inW[2]   = {(const float*)d_in[1],  (const float*)d_in[10]};
    const float* convW[2] = {(const float*)d_in[2],  (const float*)d_in[11]};
    const float* convB[2] = {(const float*)d_in[3],  (const float*)d_in[12]};
    const float* xpW[2]   = {(const float*)d_in[4],  (const float*)d_in[13]};
    const float* dtW[2]   = {(const float*)d_in[5],  (const float*)d_in[14]};
    const float* dtB[2]   = {(const float*)d_in[6],  (const float*)d_in[15]};
    const float* Alog[2]  = {(const float*)d_in[7],  (const float*)d_in[16]};
    const float* Dp[2]    = {(const float*)d_in[8],  (const float*)d_in[17]};
    const float* outW[2]  = {(const float*)d_in[9],  (const float*)d_in[18]};
    float* out = (float*)d_out;

    float *xz, *xc, *xdbl, *dt, *y;
    cudaGetSymbolAddress((void**)&xz,   g_xz);
    cudaGetSymbolAddress((void**)&xc,   g_xc);
    cudaGetSymbolAddress((void**)&xdbl, g_xdbl);
    cudaGetSymbolAddress((void**)&dt,   g_dt);
    cudaGetSymbolAddress((void**)&y,    g_y);

    const long long szXZ   = (long long)NTOK * 2 * D_INNER;
    const long long szXC   = (long long)NTOK * D_INNER;
    const long long szXDBL = (long long)NTOK * XPROJ;

    // 1) in_proj: [4096,768] x [3072,768]^T -> [4096,3072], both dirs via z
    gemm_tc<<<dim3((2 * D_INNER) / 128, NTOK / 128, 2), 256>>>(
        hidden, hidden, hidden, hidden, D_MODEL, D_MODEL,
        inW[0], inW[1], inW[0], inW[1], D_MODEL,
        xz, szXZ, 2 * D_INNER,
        2 * D_INNER, D_MODEL, nullptr, nullptr, 0);

    // 2) depthwise conv + silu
    conv_silu_kernel<<<dim3(D_INNER / 256, SEQ, 4), 256>>>(
        convW[0], convB[0], convW[1], convB[1]);

    // 3) x_proj: [4096,1536] x [80,1536]^T -> [4096,80], both dirs via z
    gemm_tc<<<dim3(1, NTOK / 128, 2), 256>>>(
        xc, xc + szXC, xc, xc + szXC, D_INNER, D_INNER,
        xpW[0], xpW[1], xpW[0], xpW[1], D_INNER,
        xdbl, szXDBL, XPROJ,
        XPROJ, D_INNER, nullptr, nullptr, 0);

    // 4) dt_proj + bias + softplus: [4096,48] x [1536,48]^T -> [4096,1536]
    gemm_tc<<<dim3(D_INNER / 128, NTOK / 128, 2), 256>>>(
        xdbl, xdbl + szXDBL, xdbl, xdbl + szXDBL, XPROJ, DT_RANK,
        dtW[0], dtW[1], dtW[0], dtW[1], DT_RANK,
        dt, szXC, D_INNER,
        D_INNER, DT_RANK, dtB[0], dtB[1], 2);

    // 5) selective scan + skip + gate
    scan_kernel<<<dim3(D_INNER / 128, BATCH, 2), 128>>>(
        Alog[0], Dp[0], Alog[1], Dp[1]);

    // 6) out_proj fused over dirs via concat-K: out = [y0|y1] @ [W0|W1]^T
    gemm_tc<<<dim3(D_MODEL / 128, NTOK / 128, 1), 256>>>(
        y, y, y + szXC, y + szXC, D_INNER, D_INNER,
        outW[0], outW[0], outW[1], outW[1], D_INNER,
        out, 0, D_MODEL,
        D_MODEL, 2 * D_INNER, nullptr, nullptr, 0);
}